// round 13
// baseline (speedup 1.0000x reference)
#include <cuda_runtime.h>
#include <cuda_bf16.h>
#include <cstdint>
#include <cstddef>

#define HH   8
#define TQ   2048
#define TT   4096
#define DK   64
#define NB   64
#define NQG    (HH*TQ)     // 16384
#define NUNITS (HH*NB)     // 512

typedef unsigned long long ull;

// Flash partials (no max shift: scores O(1), exp fp32-safe — proven R3..R11):
__device__ float  g_acc[2u * NQG * DK];
__device__ float2 g_l2[NQG];           // .x = slot0 l, .y = slot1 l
__device__ int    g_cnt[NQG];          // zero-init; second arriver resets

// bf16 hi/lo split of two floats -> packed bf16x2 (lower half = x, upper = y)
__device__ __forceinline__ void split2(float x, float y, uint32_t& hi, uint32_t& lo) {
    uint32_t h;
    asm("cvt.rn.bf16x2.f32 %0, %1, %2;" : "=r"(h) : "f"(y), "f"(x));
    float xr = x - __uint_as_float(h << 16);
    float yr = y - __uint_as_float(h & 0xFFFF0000u);
    asm("cvt.rn.bf16x2.f32 %0, %1, %2;" : "=r"(lo) : "f"(yr), "f"(xr));
    hi = h;
}

#define MMA(c0,c1,c2,c3, a0,a1,a2,a3, b0,b1)                                  \
    asm volatile("mma.sync.aligned.m16n8k16.row.col.f32.bf16.bf16.f32 "       \
        "{%0,%1,%2,%3}, {%4,%5,%6,%7}, {%8,%9}, {%0,%1,%2,%3};"               \
        : "+f"(c0), "+f"(c1), "+f"(c2), "+f"(c3)                              \
        : "r"(a0), "r"(a1), "r"(a2), "r"(a3), "r"(b0), "r"(b1))

// SMEM row strides (bytes): B-fragment LDS.32 conflict-free (see R10 notes)
#define KPITCH  144
#define VPITCH  148

__global__ __launch_bounds__(128, 3)
void partial_kernel(const float* __restrict__ q,
                    const float* __restrict__ k,
                    const float* __restrict__ v,
                    const int*   __restrict__ idx,
                    float*       __restrict__ out)
{
    __shared__ char khi[64 * KPITCH];
    __shared__ char klo[64 * KPITCH];
    __shared__ char vthi[64 * VPITCH];   // V^T: row = dim d, 64 keys bf16
    __shared__ char vtlo[64 * VPITCH];
    __shared__ unsigned short qlist[TQ];
    __shared__ int nmatch;

    const int tid  = threadIdx.x;
    const int warp = tid >> 5;           // 0..3
    const int lane = tid & 31;
    const int gid  = lane >> 2;          // mma group id (row)
    const int tig  = lane & 3;           // thread-in-group (col pair)

    const int u  = blockIdx.x;
    const int hh = u >> 6, bl = u & 63;
    if (tid == 0) nmatch = 0;

    // ---- stage K (bf16 hi/lo, [key][dk], 144B pitch) ----
    {
        const float4* kg = (const float4*)(k + ((size_t)hh * TT + (size_t)bl * 64) * DK);
        #pragma unroll 2
        for (int i = tid; i < 1024; i += 128) {
            float4 x = kg[i];
            int row = i >> 4, c = i & 15;           // dims 4c..4c+3
            uint32_t h01, l01, h23, l23;
            split2(x.x, x.y, h01, l01);
            split2(x.z, x.w, h23, l23);
            *(uint2*)(khi + row * KPITCH + c * 8) = make_uint2(h01, h23);
            *(uint2*)(klo + row * KPITCH + c * 8) = make_uint2(l01, l23);
        }
    }
    // ---- stage V^T (bf16 hi/lo, [dim][key], 148B pitch) ----
    {
        const float* vg = v + ((size_t)hh * TT + (size_t)bl * 64) * DK;
        const int d  = tid & 63;
        const int jh = (tid >> 6) * 16;             // j-pairs [jh, jh+16)
        #pragma unroll 4
        for (int jj = 0; jj < 16; jj++) {
            const int j = jh + jj;
            float a = vg[(size_t)(2 * j)     * DK + d];
            float b = vg[(size_t)(2 * j + 1) * DK + d];
            uint32_t hi, lo;
            split2(a, b, hi, lo);
            *(uint32_t*)(vthi + d * VPITCH + j * 4) = hi;
            *(uint32_t*)(vtlo + d * VPITCH + j * 4) = lo;
        }
    }
    // ---- scan this head's top2 list; warp-aggregated append ----
    {
        const int2* idxh = (const int2*)(idx + (size_t)hh * TQ * 2);
        #pragma unroll 4
        for (int qq = tid; qq < TQ; qq += 128) {
            int2 t2 = idxh[qq];
            int mk = (t2.x == bl ? 1 : 0) | (t2.y == bl ? 2 : 0);
            unsigned bal = __ballot_sync(0xFFFFFFFFu, mk != 0);
            if (mk) {
                int leader = __ffs(bal) - 1;
                int basep;
                if (lane == leader) basep = atomicAdd(&nmatch, __popc(bal));
                basep = __shfl_sync(bal, basep, leader);
                qlist[basep + __popc(bal & ((1u << lane) - 1u))] =
                    (unsigned short)(qq | (mk << 12));
            }
        }
    }
    __syncthreads();
    const int n = nmatch;

    // ---- 16-query warp tiles; 4 warps stride the tile list ----
    for (int base = warp * 16; base < n; base += 64) {
        const int e0 = base + gid, e1 = base + gid + 8;
        const unsigned short w0 = qlist[(e0 < n) ? e0 : 0];
        const unsigned short w1 = qlist[(e1 < n) ? e1 : 0];
        const int qg0 = hh * TQ + (w0 & 0x0FFF);
        const int qg1 = hh * TQ + (w1 & 0x0FFF);
        const int mk0 = (e0 < n) ? (w0 >> 12) : 0;
        const int mk1 = (e1 < n) ? (w1 >> 12) : 0;
        const float* qr0 = q + (size_t)qg0 * DK;
        const float* qr1 = q + (size_t)qg1 * DK;

        // ---- QK: S[16,64] = Q·K^T via 3-term bf16 split ----
        float sc[8][4];
        #pragma unroll
        for (int nt = 0; nt < 8; nt++)
            sc[nt][0] = sc[nt][1] = sc[nt][2] = sc[nt][3] = 0.f;

        #pragma unroll
        for (int kc = 0; kc < 4; kc++) {
            uint32_t ah[4], al[4];
            {
                float2 x0 = *(const float2*)(qr0 + kc * 16 + 2 * tig);
                float2 x1 = *(const float2*)(qr1 + kc * 16 + 2 * tig);
                float2 x2 = *(const float2*)(qr0 + kc * 16 + 2 * tig + 8);
                float2 x3 = *(const float2*)(qr1 + kc * 16 + 2 * tig + 8);
                split2(x0.x, x0.y, ah[0], al[0]);
                split2(x1.x, x1.y, ah[1], al[1]);
                split2(x2.x, x2.y, ah[2], al[2]);
                split2(x3.x, x3.y, ah[3], al[3]);
            }
            #pragma unroll
            for (int nt = 0; nt < 8; nt++) {
                const char* kb = khi + (nt * 8 + gid) * KPITCH + kc * 32 + tig * 4;
                const char* lb = klo + (nt * 8 + gid) * KPITCH + kc * 32 + tig * 4;
                uint32_t bh0 = *(const uint32_t*)(kb);
                uint32_t bh1 = *(const uint32_t*)(kb + 16);
                uint32_t bl0 = *(const uint32_t*)(lb);
                uint32_t bl1 = *(const uint32_t*)(lb + 16);
                MMA(sc[nt][0], sc[nt][1], sc[nt][2], sc[nt][3],
                    ah[0], ah[1], ah[2], ah[3], bh0, bh1);     // Qhi·Khi
                MMA(sc[nt][0], sc[nt][1], sc[nt][2], sc[nt][3],
                    al[0], al[1], al[2], al[3], bh0, bh1);     // Qlo·Khi
                MMA(sc[nt][0], sc[nt][1], sc[nt][2], sc[nt][3],
                    ah[0], ah[1], ah[2], ah[3], bl0, bl1);     // Qhi·Klo
            }
        }

        // ---- softmax partials: p = exp(s/8); l row-sums; P -> bf16 hi/lo ----
        uint32_t phi0[8], phi1[8], plo0[8], plo1[8];
        float sum0 = 0.f, sum1 = 0.f;
        #pragma unroll
        for (int nt = 0; nt < 8; nt++) {
            float p0 = __expf(sc[nt][0] * 0.125f);
            float p1 = __expf(sc[nt][1] * 0.125f);
            float p2 = __expf(sc[nt][2] * 0.125f);
            float p3 = __expf(sc[nt][3] * 0.125f);
            sum0 += p0 + p1;
            sum1 += p2 + p3;
            split2(p0, p1, phi0[nt], plo0[nt]);   // row gid
            split2(p2, p3, phi1[nt], plo1[nt]);   // row gid+8
        }
        sum0 += __shfl_xor_sync(0xFFFFFFFFu, sum0, 1);
        sum0 += __shfl_xor_sync(0xFFFFFFFFu, sum0, 2);
        sum1 += __shfl_xor_sync(0xFFFFFFFFu, sum1, 1);
        sum1 += __shfl_xor_sync(0xFFFFFFFFu, sum1, 2);

        // ---- PV: O[16,64] = P·V via 3-term split ----
        float oc[8][4];
        #pragma unroll
        for (int nt = 0; nt < 8; nt++)
            oc[nt][0] = oc[nt][1] = oc[nt][2] = oc[nt][3] = 0.f;

        #pragma unroll
        for (int kc = 0; kc < 4; kc++) {
            const uint32_t pah0 = phi0[2 * kc],     pah1 = phi1[2 * kc];
            const uint32_t pah2 = phi0[2 * kc + 1], pah3 = phi1[2 * kc + 1];
            const uint32_t pal0 = plo0[2 * kc],     pal1 = plo1[2 * kc];
            const uint32_t pal2 = plo0[2 * kc + 1], pal3 = plo1[2 * kc + 1];
            #pragma unroll
            for (int nt = 0; nt < 8; nt++) {
                const char* vb = vthi + (nt * 8 + gid) * VPITCH + kc * 32 + tig * 4;
                const char* wb = vtlo + (nt * 8 + gid) * VPITCH + kc * 32 + tig * 4;
                uint32_t bh0 = *(const uint32_t*)(vb);
                uint32_t bh1 = *(const uint32_t*)(vb + 16);
                uint32_t bl0 = *(const uint32_t*)(wb);
                uint32_t bl1 = *(const uint32_t*)(wb + 16);
                MMA(oc[nt][0], oc[nt][1], oc[nt][2], oc[nt][3],
                    pah0, pah1, pah2, pah3, bh0, bh1);         // Phi·Vhi
                MMA(oc[nt][0], oc[nt][1], oc[nt][2], oc[nt][3],
                    pal0, pal1, pal2, pal3, bh0, bh1);         // Plo·Vhi
                MMA(oc[nt][0], oc[nt][1], oc[nt][2], oc[nt][3],
                    pah0, pah1, pah2, pah3, bl0, bl1);         // Phi·Vlo
            }
        }

        // ================= finish rows =================
        // Dup rows (mk==3): both selected blocks identical -> out = acc / l.
        if (mk0 == 3) {
            const float inv = 1.0f / sum0;
            #pragma unroll
            for (int nt = 0; nt < 8; nt++)
                *(float2*)(out + (size_t)qg0 * DK + nt * 8 + 2 * tig) =
                    make_float2(oc[nt][0] * inv, oc[nt][1] * inv);
        }
        if (mk1 == 3) {
            const float inv = 1.0f / sum1;
            #pragma unroll
            for (int nt = 0; nt < 8; nt++)
                *(float2*)(out + (size_t)qg1 * DK + nt * 8 + 2 * tig) =
                    make_float2(oc[nt][2] * inv, oc[nt][3] * inv);
        }

        // Non-dup rows: store slot payload, then second arriver combines.
        const bool nd0 = (mk0 == 1) | (mk0 == 2);
        const bool nd1 = (mk1 == 1) | (mk1 == 2);
        if (nd0) {
            const int slot = mk0 - 1;
            float* pacc = g_acc + ((size_t)slot * NQG + qg0) * DK;
            #pragma unroll
            for (int nt = 0; nt < 8; nt++)
                *(float2*)(pacc + nt * 8 + 2 * tig) =
                    make_float2(oc[nt][0], oc[nt][1]);
            if (tig == 0) {
                if (slot == 0) g_l2[qg0].x = sum0; else g_l2[qg0].y = sum0;
            }
        }
        if (nd1) {
            const int slot = mk1 - 1;
            float* pacc = g_acc + ((size_t)slot * NQG + qg1) * DK;
            #pragma unroll
            for (int nt = 0; nt < 8; nt++)
                *(float2*)(pacc + nt * 8 + 2 * tig) =
                    make_float2(oc[nt][2], oc[nt][3]);
            if (tig == 0) {
                if (slot == 0) g_l2[qg1].x = sum1; else g_l2[qg1].y = sum1;
            }
        }
        if (__any_sync(0xFFFFFFFFu, nd0 | nd1)) {
            __threadfence();     // each lane: payload stores globally visible
            __syncwarp();        // ...before any quad-leader releases below
            unsigned old0 = 0, old1 = 0;
            if (tig == 0) {
                if (nd0)
                    asm volatile("atom.acq_rel.gpu.global.add.u32 %0, [%1], %2;"
                                 : "=r"(old0) : "l"(g_cnt + qg0), "r"(1u) : "memory");
                if (nd1)
                    asm volatile("atom.acq_rel.gpu.global.add.u32 %0, [%1], %2;"
                                 : "=r"(old1) : "l"(g_cnt + qg1), "r"(1u) : "memory");
            }
            old0 = __shfl_sync(0xFFFFFFFFu, old0, lane & ~3);   // quad broadcast
            old1 = __shfl_sync(0xFFFFFFFFu, old1, lane & ~3);
            if (nd0 && old0 == 1) {                    // we arrived second: combine
                const int ps = 2 - mk0;                // partner slot
                const float lp = (ps == 0) ? __ldcg(&g_l2[qg0].x) : __ldcg(&g_l2[qg0].y);
                const float inv = 1.0f / (sum0 + lp);
                const float* pa = g_acc + ((size_t)ps * NQG + qg0) * DK;
                #pragma unroll
                for (int nt = 0; nt < 8; nt++) {
                    float2 pp = __ldcg((const float2*)(pa + nt * 8 + 2 * tig));
                    *(float2*)(out + (size_t)qg0 * DK + nt * 8 + 2 * tig) =
                        make_float2((oc[nt][0] + pp.x) * inv,
                                    (oc[nt][1] + pp.y) * inv);
                }
                if (tig == 0) g_cnt[qg0] = 0;          // reset for next replay
            }
            if (nd1 && old1 == 1) {
                const int ps = 2 - mk1;
                const float lp = (ps == 0) ? __ldcg(&g_l2[qg1].x) : __ldcg(&g_l2[qg1].y);
                const float inv = 1.0f / (sum1 + lp);
                const float* pa = g_acc + ((size_t)ps * NQG + qg1) * DK;
                #pragma unroll
                for (int nt = 0; nt < 8; nt++) {
                    float2 pp = __ldcg((const float2*)(pa + nt * 8 + 2 * tig));
                    *(float2*)(out + (size_t)qg1 * DK + nt * 8 + 2 * tig) =
                        make_float2((oc[nt][2] + pp.x) * inv,
                                    (oc[nt][3] + pp.y) * inv);
                }
                if (tig == 0) g_cnt[qg1] = 0;
            }
        }
    }
}

// ---------------------------------------------------------------------------
extern "C" void kernel_launch(void* const* d_in, const int* in_sizes, int n_in,
                              void* d_out, int out_size)
{
    const float* q = nullptr; const float* k = nullptr; const float* v = nullptr;
    const int* idx = nullptr;
    for (int i = 0; i < n_in; i++) {
        const int s = in_sizes[i];
        if (s == HH * TQ * DK && !q)  q = (const float*)d_in[i];       // 1,048,576
        else if (s == HH * TT * DK) {                                   // 2,097,152
            if (!k) k = (const float*)d_in[i];
            else if (!v) v = (const float*)d_in[i];
        }
        else if (s == HH * TQ * 2)    idx = (const int*)d_in[i];        // 32,768
    }

    partial_kernel<<<NUNITS, 128>>>(q, k, v, idx, (float*)d_out);
}

// round 14
// speedup vs baseline: 1.8693x; 1.8693x over previous
#include <cuda_runtime.h>
#include <cuda_bf16.h>
#include <cstdint>
#include <cstddef>

#define HH   8
#define TQ   2048
#define TT   4096
#define DK   64
#define NB   64
#define NQG    (HH*TQ)     // 16384
#define NUNITS (HH*NB)     // 512

typedef unsigned long long ull;

// Flash partials (no max shift: scores O(1), exp fp32-safe — proven R3..R12):
__device__ float  g_acc[2u * NQG * DK];
__device__ float2 g_l2[NQG];

// bf16 hi/lo split of two floats -> packed bf16x2 (lower half = x, upper = y)
__device__ __forceinline__ void split2(float x, float y, uint32_t& hi, uint32_t& lo) {
    uint32_t h;
    asm("cvt.rn.bf16x2.f32 %0, %1, %2;" : "=r"(h) : "f"(y), "f"(x));
    float xr = x - __uint_as_float(h << 16);
    float yr = y - __uint_as_float(h & 0xFFFF0000u);
    asm("cvt.rn.bf16x2.f32 %0, %1, %2;" : "=r"(lo) : "f"(yr), "f"(xr));
    hi = h;
}

#define MMA(c0,c1,c2,c3, a0,a1,a2,a3, b0,b1)                                  \
    asm volatile("mma.sync.aligned.m16n8k16.row.col.f32.bf16.bf16.f32 "       \
        "{%0,%1,%2,%3}, {%4,%5,%6,%7}, {%8,%9}, {%0,%1,%2,%3};"               \
        : "+f"(c0), "+f"(c1), "+f"(c2), "+f"(c3)                              \
        : "r"(a0), "r"(a1), "r"(a2), "r"(a3), "r"(b0), "r"(b1))

// SMEM row strides (bytes): B-fragment LDS.32 conflict-free:
//   K rows 144B  -> bank(lane) = 4*gid + t  (all 32 distinct)
//   VT rows 148B -> staging STS conflict-free, LDS ~1.06-way
#define KPITCH  144
#define VPITCH  148

__global__ __launch_bounds__(128, 4)
void partial_kernel(const float* __restrict__ q,
                    const float* __restrict__ k,
                    const float* __restrict__ v,
                    const int*   __restrict__ idx)
{
    __shared__ char khi[64 * KPITCH];
    __shared__ char klo[64 * KPITCH];
    __shared__ char vthi[64 * VPITCH];   // V^T: row = dim d, 64 keys bf16
    __shared__ char vtlo[64 * VPITCH];
    __shared__ unsigned short qlist[TQ];
    __shared__ int nmatch;

    const int tid  = threadIdx.x;
    const int warp = tid >> 5;           // 0..3
    const int lane = tid & 31;
    const int gid  = lane >> 2;          // mma group id (row)
    const int tig  = lane & 3;           // thread-in-group (col pair)

    const int u  = blockIdx.x;
    const int hh = u >> 6, bl = u & 63;
    if (tid == 0) nmatch = 0;

    // ---- stage K (bf16 hi/lo, [key][dk], 144B pitch) ----
    {
        const float4* kg = (const float4*)(k + ((size_t)hh * TT + (size_t)bl * 64) * DK);
        #pragma unroll 2
        for (int i = tid; i < 1024; i += 128) {
            float4 x = kg[i];
            int row = i >> 4, c = i & 15;           // dims 4c..4c+3
            uint32_t h01, l01, h23, l23;
            split2(x.x, x.y, h01, l01);
            split2(x.z, x.w, h23, l23);
            *(uint2*)(khi + row * KPITCH + c * 8) = make_uint2(h01, h23);
            *(uint2*)(klo + row * KPITCH + c * 8) = make_uint2(l01, l23);
        }
    }
    // ---- stage V^T (bf16 hi/lo, [dim][key], 148B pitch) ----
    {
        const float* vg = v + ((size_t)hh * TT + (size_t)bl * 64) * DK;
        const int d  = tid & 63;
        const int jh = (tid >> 6) * 16;             // j-pairs [jh, jh+16)
        #pragma unroll 4
        for (int jj = 0; jj < 16; jj++) {
            const int j = jh + jj;
            float a = vg[(size_t)(2 * j)     * DK + d];
            float b = vg[(size_t)(2 * j + 1) * DK + d];
            uint32_t hi, lo;
            split2(a, b, hi, lo);
            *(uint32_t*)(vthi + d * VPITCH + j * 4) = hi;
            *(uint32_t*)(vtlo + d * VPITCH + j * 4) = lo;
        }
    }
    // ---- scan this head's top2 list; warp-aggregated append ----
    {
        const int2* idxh = (const int2*)(idx + (size_t)hh * TQ * 2);
        #pragma unroll 4
        for (int qq = tid; qq < TQ; qq += 128) {
            int2 t2 = idxh[qq];
            int mk = (t2.x == bl ? 1 : 0) | (t2.y == bl ? 2 : 0);
            unsigned bal = __ballot_sync(0xFFFFFFFFu, mk != 0);
            if (mk) {
                int leader = __ffs(bal) - 1;
                int basep;
                if (lane == leader) basep = atomicAdd(&nmatch, __popc(bal));
                basep = __shfl_sync(bal, basep, leader);
                qlist[basep + __popc(bal & ((1u << lane) - 1u))] =
                    (unsigned short)(qq | (mk << 12));
            }
        }
    }
    __syncthreads();
    const int n = nmatch;

    // ---- 16-query warp tiles; 4 warps stride the tile list ----
    for (int base = warp * 16; base < n; base += 64) {
        // rows this thread touches: gid and gid+8
        const int e0 = base + gid, e1 = base + gid + 8;
        const unsigned short w0 = qlist[(e0 < n) ? e0 : 0];
        const unsigned short w1 = qlist[(e1 < n) ? e1 : 0];
        const int qg0 = hh * TQ + (w0 & 0x0FFF);
        const int qg1 = hh * TQ + (w1 & 0x0FFF);
        const int mk0 = (e0 < n) ? (w0 >> 12) : 0;
        const int mk1 = (e1 < n) ? (w1 >> 12) : 0;
        const float* qr0 = q + (size_t)qg0 * DK;
        const float* qr1 = q + (size_t)qg1 * DK;

        // ---- QK: S[16,64] = Q·K^T via 3-term bf16 split ----
        float sc[8][4];
        #pragma unroll
        for (int nt = 0; nt < 8; nt++)
            sc[nt][0] = sc[nt][1] = sc[nt][2] = sc[nt][3] = 0.f;

        #pragma unroll
        for (int kc = 0; kc < 4; kc++) {
            uint32_t ah[4], al[4];
            {
                float2 x0 = *(const float2*)(qr0 + kc * 16 + 2 * tig);
                float2 x1 = *(const float2*)(qr1 + kc * 16 + 2 * tig);
                float2 x2 = *(const float2*)(qr0 + kc * 16 + 2 * tig + 8);
                float2 x3 = *(const float2*)(qr1 + kc * 16 + 2 * tig + 8);
                split2(x0.x, x0.y, ah[0], al[0]);
                split2(x1.x, x1.y, ah[1], al[1]);
                split2(x2.x, x2.y, ah[2], al[2]);
                split2(x3.x, x3.y, ah[3], al[3]);
            }
            #pragma unroll
            for (int nt = 0; nt < 8; nt++) {
                const char* kb = khi + (nt * 8 + gid) * KPITCH + kc * 32 + tig * 4;
                const char* lb = klo + (nt * 8 + gid) * KPITCH + kc * 32 + tig * 4;
                uint32_t bh0 = *(const uint32_t*)(kb);
                uint32_t bh1 = *(const uint32_t*)(kb + 16);
                uint32_t bl0 = *(const uint32_t*)(lb);
                uint32_t bl1 = *(const uint32_t*)(lb + 16);
                MMA(sc[nt][0], sc[nt][1], sc[nt][2], sc[nt][3],
                    ah[0], ah[1], ah[2], ah[3], bh0, bh1);     // Qhi·Khi
                MMA(sc[nt][0], sc[nt][1], sc[nt][2], sc[nt][3],
                    al[0], al[1], al[2], al[3], bh0, bh1);     // Qlo·Khi
                MMA(sc[nt][0], sc[nt][1], sc[nt][2], sc[nt][3],
                    ah[0], ah[1], ah[2], ah[3], bl0, bl1);     // Qhi·Klo
            }
        }

        // ---- softmax partials: p = exp(s/8); l row-sums; P -> bf16 hi/lo ----
        uint32_t phi0[8], phi1[8], plo0[8], plo1[8];
        float sum0 = 0.f, sum1 = 0.f;
        #pragma unroll
        for (int nt = 0; nt < 8; nt++) {
            float p0 = __expf(sc[nt][0] * 0.125f);
            float p1 = __expf(sc[nt][1] * 0.125f);
            float p2 = __expf(sc[nt][2] * 0.125f);
            float p3 = __expf(sc[nt][3] * 0.125f);
            sum0 += p0 + p1;
            sum1 += p2 + p3;
            split2(p0, p1, phi0[nt], plo0[nt]);   // row gid
            split2(p2, p3, phi1[nt], plo1[nt]);   // row gid+8
        }
        sum0 += __shfl_xor_sync(0xFFFFFFFFu, sum0, 1);
        sum0 += __shfl_xor_sync(0xFFFFFFFFu, sum0, 2);
        sum1 += __shfl_xor_sync(0xFFFFFFFFu, sum1, 1);
        sum1 += __shfl_xor_sync(0xFFFFFFFFu, sum1, 2);

        // ---- PV: O[16,64] = P·V via 3-term split ----
        float oc[8][4];
        #pragma unroll
        for (int nt = 0; nt < 8; nt++)
            oc[nt][0] = oc[nt][1] = oc[nt][2] = oc[nt][3] = 0.f;

        #pragma unroll
        for (int kc = 0; kc < 4; kc++) {
            // A fragment (P) chunk kc = S n-tiles 2kc, 2kc+1 (direct mapping)
            const uint32_t pah0 = phi0[2 * kc],     pah1 = phi1[2 * kc];
            const uint32_t pah2 = phi0[2 * kc + 1], pah3 = phi1[2 * kc + 1];
            const uint32_t pal0 = plo0[2 * kc],     pal1 = plo1[2 * kc];
            const uint32_t pal2 = plo0[2 * kc + 1], pal3 = plo1[2 * kc + 1];
            #pragma unroll
            for (int nt = 0; nt < 8; nt++) {
                const char* vb = vthi + (nt * 8 + gid) * VPITCH + kc * 32 + tig * 4;
                const char* wb = vtlo + (nt * 8 + gid) * VPITCH + kc * 32 + tig * 4;
                uint32_t bh0 = *(const uint32_t*)(vb);
                uint32_t bh1 = *(const uint32_t*)(vb + 16);
                uint32_t bl0 = *(const uint32_t*)(wb);
                uint32_t bl1 = *(const uint32_t*)(wb + 16);
                MMA(oc[nt][0], oc[nt][1], oc[nt][2], oc[nt][3],
                    pah0, pah1, pah2, pah3, bh0, bh1);         // Phi·Vhi
                MMA(oc[nt][0], oc[nt][1], oc[nt][2], oc[nt][3],
                    pal0, pal1, pal2, pal3, bh0, bh1);         // Plo·Vhi
                MMA(oc[nt][0], oc[nt][1], oc[nt][2], oc[nt][3],
                    pah0, pah1, pah2, pah3, bl0, bl1);         // Phi·Vlo
            }
        }

        // ---- store flash partials (unnormalized; dup mk==3 fills both) ----
        #pragma unroll
        for (int slot = 0; slot < 2; slot++) {
            const size_t sbase = (size_t)slot * NQG * DK;
            if (mk0 & (1 << slot)) {
                #pragma unroll
                for (int nt = 0; nt < 8; nt++)
                    *(float2*)(g_acc + sbase + (size_t)qg0 * DK + nt * 8 + 2 * tig) =
                        make_float2(oc[nt][0], oc[nt][1]);
                if (tig == 0) {
                    if (slot == 0) g_l2[qg0].x = sum0; else g_l2[qg0].y = sum0;
                }
            }
            if (mk1 & (1 << slot)) {
                #pragma unroll
                for (int nt = 0; nt < 8; nt++)
                    *(float2*)(g_acc + sbase + (size_t)qg1 * DK + nt * 8 + 2 * tig) =
                        make_float2(oc[nt][2], oc[nt][3]);
                if (tig == 0) {
                    if (slot == 0) g_l2[qg1].x = sum1; else g_l2[qg1].y = sum1;
                }
            }
        }
    }
}

// ---------------------------------------------------------------------------
// Combine: out = (acc0 + acc1) / (l0 + l1). Best-measured config (R10).
// ---------------------------------------------------------------------------
__global__ __launch_bounds__(256)
void combine_kernel(float* __restrict__ out)
{
    const int t  = blockIdx.x * 256 + threadIdx.x;
    const int qg = t >> 4;
    const float2 ll = g_l2[qg];
    const float4 a  = ((const float4*)g_acc)[t];
    const float4 b  = ((const float4*)g_acc)[NQG * 16 + t];
    const float inv = 1.0f / (ll.x + ll.y);
    float4 o;
    o.x = (a.x + b.x) * inv;
    o.y = (a.y + b.y) * inv;
    o.z = (a.z + b.z) * inv;
    o.w = (a.w + b.w) * inv;
    ((float4*)out)[t] = o;
}

// ---------------------------------------------------------------------------
extern "C" void kernel_launch(void* const* d_in, const int* in_sizes, int n_in,
                              void* d_out, int out_size)
{
    const float* q = nullptr; const float* k = nullptr; const float* v = nullptr;
    const int* idx = nullptr;
    for (int i = 0; i < n_in; i++) {
        const int s = in_sizes[i];
        if (s == HH * TQ * DK && !q)  q = (const float*)d_in[i];       // 1,048,576
        else if (s == HH * TT * DK) {                                   // 2,097,152
            if (!k) k = (const float*)d_in[i];
            else if (!v) v = (const float*)d_in[i];
        }
        else if (s == HH * TQ * 2)    idx = (const int*)d_in[i];        // 32,768
    }

    partial_kernel<<<NUNITS, 128>>>(q, k, v, idx);
    combine_kernel<<<(NQG * 16) / 256, 256>>>((float*)d_out);
}

// round 15
// speedup vs baseline: 2.0716x; 1.1082x over previous
#include <cuda_runtime.h>
#include <cuda_bf16.h>
#include <cstdint>
#include <cstddef>

#define HH   8
#define TQ   2048
#define TT   4096
#define DK   64
#define NB   64
#define NQG    (HH*TQ)     // 16384
#define NUNITS (HH*NB)     // 512
#define BKCAP  4096        // bucket capacity (theoretical max; no overflow possible)

typedef unsigned long long ull;

// Flash partials (no max shift: scores O(1), exp fp32-safe — proven R3..R13):
__device__ float  g_acc[2u * NQG * DK];
__device__ float2 g_l2[NQG];

// Bucketed query lists, built by bucket_kernel each replay:
__device__ int            g_bcnt[NUNITS];          // zero-init; combine resets
__device__ unsigned short g_qbuf[NUNITS * BKCAP];  // entries: qq | mk<<12

// bf16 hi/lo split of two floats -> packed bf16x2 (lower half = x, upper = y)
__device__ __forceinline__ void split2(float x, float y, uint32_t& hi, uint32_t& lo) {
    uint32_t h;
    asm("cvt.rn.bf16x2.f32 %0, %1, %2;" : "=r"(h) : "f"(y), "f"(x));
    float xr = x - __uint_as_float(h << 16);
    float yr = y - __uint_as_float(h & 0xFFFF0000u);
    asm("cvt.rn.bf16x2.f32 %0, %1, %2;" : "=r"(lo) : "f"(yr), "f"(xr));
    hi = h;
}

#define MMA(c0,c1,c2,c3, a0,a1,a2,a3, b0,b1)                                  \
    asm volatile("mma.sync.aligned.m16n8k16.row.col.f32.bf16.bf16.f32 "       \
        "{%0,%1,%2,%3}, {%4,%5,%6,%7}, {%8,%9}, {%0,%1,%2,%3};"               \
        : "+f"(c0), "+f"(c1), "+f"(c2), "+f"(c3)                              \
        : "r"(a0), "r"(a1), "r"(a2), "r"(a3), "r"(b0), "r"(b1))

// SMEM row strides (bytes): B-fragment LDS.32 conflict-free (R10-proven)
#define KPITCH  144
#define VPITCH  148

// ---------------------------------------------------------------------------
// Prepass: bucket each query's top2 picks by (head, block).
// ---------------------------------------------------------------------------
__global__ __launch_bounds__(256)
void bucket_kernel(const int* __restrict__ idx)
{
    const int qg = blockIdx.x * 256 + threadIdx.x;     // 0..16383
    const int hh = qg >> 11, qq = qg & 2047;
    const int2 t2 = ((const int2*)idx)[qg];
    const int u0 = (hh << 6) | t2.x;
    if (t2.x == t2.y) {
        int p = atomicAdd(&g_bcnt[u0], 1);
        g_qbuf[(size_t)u0 * BKCAP + p] = (unsigned short)(qq | (3 << 12));
    } else {
        const int u1 = (hh << 6) | t2.y;
        int p0 = atomicAdd(&g_bcnt[u0], 1);
        g_qbuf[(size_t)u0 * BKCAP + p0] = (unsigned short)(qq | (1 << 12));
        int p1 = atomicAdd(&g_bcnt[u1], 1);
        g_qbuf[(size_t)u1 * BKCAP + p1] = (unsigned short)(qq | (2 << 12));
    }
}

// ---------------------------------------------------------------------------
__global__ __launch_bounds__(128, 4)
void partial_kernel(const float* __restrict__ q,
                    const float* __restrict__ k,
                    const float* __restrict__ v)
{
    __shared__ char khi[64 * KPITCH];
    __shared__ char klo[64 * KPITCH];
    __shared__ char vthi[64 * VPITCH];   // V^T: row = dim d, 64 keys bf16
    __shared__ char vtlo[64 * VPITCH];

    const int tid  = threadIdx.x;
    const int warp = tid >> 5;           // 0..3
    const int lane = tid & 31;
    const int gid  = lane >> 2;          // mma group id (row)
    const int tig  = lane & 3;           // thread-in-group (col pair)

    const int u  = blockIdx.x;
    const int hh = u >> 6, bl = u & 63;
    const unsigned short* qbuf = g_qbuf + (size_t)u * BKCAP;
    const int n = g_bcnt[u];             // broadcast L2 read

    // ---- stage K (bf16 hi/lo, [key][dk], 144B pitch) ----
    {
        const float4* kg = (const float4*)(k + ((size_t)hh * TT + (size_t)bl * 64) * DK);
        #pragma unroll 2
        for (int i = tid; i < 1024; i += 128) {
            float4 x = kg[i];
            int row = i >> 4, c = i & 15;           // dims 4c..4c+3
            uint32_t h01, l01, h23, l23;
            split2(x.x, x.y, h01, l01);
            split2(x.z, x.w, h23, l23);
            *(uint2*)(khi + row * KPITCH + c * 8) = make_uint2(h01, h23);
            *(uint2*)(klo + row * KPITCH + c * 8) = make_uint2(l01, l23);
        }
    }
    // ---- stage V^T (bf16 hi/lo, [dim][key], 148B pitch) ----
    {
        const float* vg = v + ((size_t)hh * TT + (size_t)bl * 64) * DK;
        const int d  = tid & 63;
        const int jh = (tid >> 6) * 16;             // j-pairs [jh, jh+16)
        #pragma unroll 4
        for (int jj = 0; jj < 16; jj++) {
            const int j = jh + jj;
            float a = vg[(size_t)(2 * j)     * DK + d];
            float b = vg[(size_t)(2 * j + 1) * DK + d];
            uint32_t hi, lo;
            split2(a, b, hi, lo);
            *(uint32_t*)(vthi + d * VPITCH + j * 4) = hi;
            *(uint32_t*)(vtlo + d * VPITCH + j * 4) = lo;
        }
    }
    __syncthreads();

    // ---- 16-query warp tiles; 4 warps stride the tile list ----
    for (int base = warp * 16; base < n; base += 64) {
        // rows this thread touches: gid and gid+8
        const int e0 = base + gid, e1 = base + gid + 8;
        const unsigned short w0 = qbuf[(e0 < n) ? e0 : 0];
        const unsigned short w1 = qbuf[(e1 < n) ? e1 : 0];
        const int qg0 = hh * TQ + (w0 & 0x0FFF);
        const int qg1 = hh * TQ + (w1 & 0x0FFF);
        const int mk0 = (e0 < n) ? (w0 >> 12) : 0;
        const int mk1 = (e1 < n) ? (w1 >> 12) : 0;
        const float* qr0 = q + (size_t)qg0 * DK;
        const float* qr1 = q + (size_t)qg1 * DK;

        // ---- QK: S[16,64] = Q·K^T via 3-term bf16 split ----
        float sc[8][4];
        #pragma unroll
        for (int nt = 0; nt < 8; nt++)
            sc[nt][0] = sc[nt][1] = sc[nt][2] = sc[nt][3] = 0.f;

        #pragma unroll
        for (int kc = 0; kc < 4; kc++) {
            uint32_t ah[4], al[4];
            {
                float2 x0 = *(const float2*)(qr0 + kc * 16 + 2 * tig);
                float2 x1 = *(const float2*)(qr1 + kc * 16 + 2 * tig);
                float2 x2 = *(const float2*)(qr0 + kc * 16 + 2 * tig + 8);
                float2 x3 = *(const float2*)(qr1 + kc * 16 + 2 * tig + 8);
                split2(x0.x, x0.y, ah[0], al[0]);
                split2(x1.x, x1.y, ah[1], al[1]);
                split2(x2.x, x2.y, ah[2], al[2]);
                split2(x3.x, x3.y, ah[3], al[3]);
            }
            #pragma unroll
            for (int nt = 0; nt < 8; nt++) {
                const char* kb = khi + (nt * 8 + gid) * KPITCH + kc * 32 + tig * 4;
                const char* lb = klo + (nt * 8 + gid) * KPITCH + kc * 32 + tig * 4;
                uint32_t bh0 = *(const uint32_t*)(kb);
                uint32_t bh1 = *(const uint32_t*)(kb + 16);
                uint32_t bl0 = *(const uint32_t*)(lb);
                uint32_t bl1 = *(const uint32_t*)(lb + 16);
                MMA(sc[nt][0], sc[nt][1], sc[nt][2], sc[nt][3],
                    ah[0], ah[1], ah[2], ah[3], bh0, bh1);     // Qhi·Khi
                MMA(sc[nt][0], sc[nt][1], sc[nt][2], sc[nt][3],
                    al[0], al[1], al[2], al[3], bh0, bh1);     // Qlo·Khi
                MMA(sc[nt][0], sc[nt][1], sc[nt][2], sc[nt][3],
                    ah[0], ah[1], ah[2], ah[3], bl0, bl1);     // Qhi·Klo
            }
        }

        // ---- softmax partials: p = exp(s/8); l row-sums; P -> bf16 hi/lo ----
        uint32_t phi0[8], phi1[8], plo0[8], plo1[8];
        float sum0 = 0.f, sum1 = 0.f;
        #pragma unroll
        for (int nt = 0; nt < 8; nt++) {
            float p0 = __expf(sc[nt][0] * 0.125f);
            float p1 = __expf(sc[nt][1] * 0.125f);
            float p2 = __expf(sc[nt][2] * 0.125f);
            float p3 = __expf(sc[nt][3] * 0.125f);
            sum0 += p0 + p1;
            sum1 += p2 + p3;
            split2(p0, p1, phi0[nt], plo0[nt]);   // row gid
            split2(p2, p3, phi1[nt], plo1[nt]);   // row gid+8
        }
        sum0 += __shfl_xor_sync(0xFFFFFFFFu, sum0, 1);
        sum0 += __shfl_xor_sync(0xFFFFFFFFu, sum0, 2);
        sum1 += __shfl_xor_sync(0xFFFFFFFFu, sum1, 1);
        sum1 += __shfl_xor_sync(0xFFFFFFFFu, sum1, 2);

        // ---- PV: O[16,64] = P·V via 3-term split ----
        float oc[8][4];
        #pragma unroll
        for (int nt = 0; nt < 8; nt++)
            oc[nt][0] = oc[nt][1] = oc[nt][2] = oc[nt][3] = 0.f;

        #pragma unroll
        for (int kc = 0; kc < 4; kc++) {
            // A fragment (P) chunk kc = S n-tiles 2kc, 2kc+1 (direct mapping)
            const uint32_t pah0 = phi0[2 * kc],     pah1 = phi1[2 * kc];
            const uint32_t pah2 = phi0[2 * kc + 1], pah3 = phi1[2 * kc + 1];
            const uint32_t pal0 = plo0[2 * kc],     pal1 = plo1[2 * kc];
            const uint32_t pal2 = plo0[2 * kc + 1], pal3 = plo1[2 * kc + 1];
            #pragma unroll
            for (int nt = 0; nt < 8; nt++) {
                const char* vb = vthi + (nt * 8 + gid) * VPITCH + kc * 32 + tig * 4;
                const char* wb = vtlo + (nt * 8 + gid) * VPITCH + kc * 32 + tig * 4;
                uint32_t bh0 = *(const uint32_t*)(vb);
                uint32_t bh1 = *(const uint32_t*)(vb + 16);
                uint32_t bl0 = *(const uint32_t*)(wb);
                uint32_t bl1 = *(const uint32_t*)(wb + 16);
                MMA(oc[nt][0], oc[nt][1], oc[nt][2], oc[nt][3],
                    pah0, pah1, pah2, pah3, bh0, bh1);         // Phi·Vhi
                MMA(oc[nt][0], oc[nt][1], oc[nt][2], oc[nt][3],
                    pal0, pal1, pal2, pal3, bh0, bh1);         // Plo·Vhi
                MMA(oc[nt][0], oc[nt][1], oc[nt][2], oc[nt][3],
                    pah0, pah1, pah2, pah3, bl0, bl1);         // Phi·Vlo
            }
        }

        // ---- store flash partials (unnormalized; dup mk==3 fills both) ----
        #pragma unroll
        for (int slot = 0; slot < 2; slot++) {
            const size_t sbase = (size_t)slot * NQG * DK;
            if (mk0 & (1 << slot)) {
                #pragma unroll
                for (int nt = 0; nt < 8; nt++)
                    *(float2*)(g_acc + sbase + (size_t)qg0 * DK + nt * 8 + 2 * tig) =
                        make_float2(oc[nt][0], oc[nt][1]);
                if (tig == 0) {
                    if (slot == 0) g_l2[qg0].x = sum0; else g_l2[qg0].y = sum0;
                }
            }
            if (mk1 & (1 << slot)) {
                #pragma unroll
                for (int nt = 0; nt < 8; nt++)
                    *(float2*)(g_acc + sbase + (size_t)qg1 * DK + nt * 8 + 2 * tig) =
                        make_float2(oc[nt][2], oc[nt][3]);
                if (tig == 0) {
                    if (slot == 0) g_l2[qg1].x = sum1; else g_l2[qg1].y = sum1;
                }
            }
        }
    }
}

// ---------------------------------------------------------------------------
// Combine: out = (acc0 + acc1) / (l0 + l1). Block 0 resets bucket counters
// for the next graph replay (runs strictly after partial on the stream).
// ---------------------------------------------------------------------------
__global__ __launch_bounds__(256)
void combine_kernel(float* __restrict__ out)
{
    if (blockIdx.x == 0 && threadIdx.x < NUNITS / 2) {
        g_bcnt[threadIdx.x] = 0;
        g_bcnt[threadIdx.x + NUNITS / 2] = 0;
    }
    const int t  = blockIdx.x * 256 + threadIdx.x;
    const int qg = t >> 4;
    const float2 ll = g_l2[qg];
    const float4 a  = ((const float4*)g_acc)[t];
    const float4 b  = ((const float4*)g_acc)[NQG * 16 + t];
    const float inv = 1.0f / (ll.x + ll.y);
    float4 o;
    o.x = (a.x + b.x) * inv;
    o.y = (a.y + b.y) * inv;
    o.z = (a.z + b.z) * inv;
    o.w = (a.w + b.w) * inv;
    ((float4*)out)[t] = o;
}

// ---------------------------------------------------------------------------
extern "C" void kernel_launch(void* const* d_in, const int* in_sizes, int n_in,
                              void* d_out, int out_size)
{
    const float* q = nullptr; const float* k = nullptr; const float* v = nullptr;
    const int* idx = nullptr;
    for (int i = 0; i < n_in; i++) {
        const int s = in_sizes[i];
        if (s == HH * TQ * DK && !q)  q = (const float*)d_in[i];       // 1,048,576
        else if (s == HH * TT * DK) {                                   // 2,097,152
            if (!k) k = (const float*)d_in[i];
            else if (!v) v = (const float*)d_in[i];
        }
        else if (s == HH * TQ * 2)    idx = (const int*)d_in[i];        // 32,768
    }

    bucket_kernel<<<NQG / 256, 256>>>(idx);
    partial_kernel<<<NUNITS, 128>>>(q, k, v);
    combine_kernel<<<(NQG * 16) / 256, 256>>>((float*)d_out);
}

// round 16
// speedup vs baseline: 2.1990x; 1.0615x over previous
#include <cuda_runtime.h>
#include <cuda_bf16.h>
#include <cstdint>
#include <cstddef>

#define HH   8
#define TQ   2048
#define TT   4096
#define DK   64
#define NB   64
#define NQG    (HH*TQ)     // 16384
#define NUNITS (HH*NB)     // 512
#define BKCAP  4096        // bucket capacity (theoretical max; no overflow possible)

typedef unsigned long long ull;

// Flash partials (no max shift: scores O(1), exp fp32-safe — proven R3..R14):
__device__ float  g_acc[2u * NQG * DK];
__device__ float2 g_l2[NQG];

// Bucketed query lists, rebuilt by bucket_kernel each replay:
__device__ int            g_bcnt[NUNITS];          // zero-init; combine resets
__device__ unsigned short g_qbuf[NUNITS * BKCAP];  // entries: qq | mk<<12

// bf16 hi/lo split of two floats -> packed bf16x2 (lower half = x, upper = y)
__device__ __forceinline__ void split2(float x, float y, uint32_t& hi, uint32_t& lo) {
    uint32_t h;
    asm("cvt.rn.bf16x2.f32 %0, %1, %2;" : "=r"(h) : "f"(y), "f"(x));
    float xr = x - __uint_as_float(h << 16);
    float yr = y - __uint_as_float(h & 0xFFFF0000u);
    asm("cvt.rn.bf16x2.f32 %0, %1, %2;" : "=r"(lo) : "f"(yr), "f"(xr));
    hi = h;
}

#define MMA(c0,c1,c2,c3, a0,a1,a2,a3, b0,b1)                                  \
    asm volatile("mma.sync.aligned.m16n8k16.row.col.f32.bf16.bf16.f32 "       \
        "{%0,%1,%2,%3}, {%4,%5,%6,%7}, {%8,%9}, {%0,%1,%2,%3};"               \
        : "+f"(c0), "+f"(c1), "+f"(c2), "+f"(c3)                              \
        : "r"(a0), "r"(a1), "r"(a2), "r"(a3), "r"(b0), "r"(b1))

// SMEM row strides (bytes): B-fragment LDS.32 conflict-free (R10-proven)
#define KPITCH  144
#define VPITCH  148

// ---------------------------------------------------------------------------
// Prepass: bucket each query's top2 picks by (head, block).
// Triggers PDL completion immediately: downstream gridDependencySynchronize
// waits for full grid completion, so our writes are safe; the early trigger
// lets partial_kernel's CTAs launch and stage K/V concurrently.
// ---------------------------------------------------------------------------
__global__ __launch_bounds__(256)
void bucket_kernel(const int* __restrict__ idx)
{
    cudaTriggerProgrammaticLaunchCompletion();
    const int qg = blockIdx.x * 256 + threadIdx.x;     // 0..16383
    const int hh = qg >> 11, qq = qg & 2047;
    const int2 t2 = ((const int2*)idx)[qg];
    const int u0 = (hh << 6) | t2.x;
    if (t2.x == t2.y) {
        int p = atomicAdd(&g_bcnt[u0], 1);
        g_qbuf[(size_t)u0 * BKCAP + p] = (unsigned short)(qq | (3 << 12));
    } else {
        const int u1 = (hh << 6) | t2.y;
        int p0 = atomicAdd(&g_bcnt[u0], 1);
        g_qbuf[(size_t)u0 * BKCAP + p0] = (unsigned short)(qq | (1 << 12));
        int p1 = atomicAdd(&g_bcnt[u1], 1);
        g_qbuf[(size_t)u1 * BKCAP + p1] = (unsigned short)(qq | (2 << 12));
    }
}

// ---------------------------------------------------------------------------
__global__ __launch_bounds__(128, 4)
void partial_kernel(const float* __restrict__ q,
                    const float* __restrict__ k,
                    const float* __restrict__ v)
{
    __shared__ char khi[64 * KPITCH];
    __shared__ char klo[64 * KPITCH];
    __shared__ char vthi[64 * VPITCH];   // V^T: row = dim d, 64 keys bf16
    __shared__ char vtlo[64 * VPITCH];

    const int tid  = threadIdx.x;
    const int warp = tid >> 5;           // 0..3
    const int lane = tid & 31;
    const int gid  = lane >> 2;          // mma group id (row)
    const int tig  = lane & 3;           // thread-in-group (col pair)

    const int u  = blockIdx.x;
    const int hh = u >> 6, bl = u & 63;

    // ---- stage K (bf16 hi/lo, [key][dk], 144B pitch) — bucket-independent ----
    {
        const float4* kg = (const float4*)(k + ((size_t)hh * TT + (size_t)bl * 64) * DK);
        #pragma unroll 2
        for (int i = tid; i < 1024; i += 128) {
            float4 x = kg[i];
            int row = i >> 4, c = i & 15;           // dims 4c..4c+3
            uint32_t h01, l01, h23, l23;
            split2(x.x, x.y, h01, l01);
            split2(x.z, x.w, h23, l23);
            *(uint2*)(khi + row * KPITCH + c * 8) = make_uint2(h01, h23);
            *(uint2*)(klo + row * KPITCH + c * 8) = make_uint2(l01, l23);
        }
    }
    // ---- stage V^T (bf16 hi/lo, [dim][key], 148B pitch) ----
    {
        const float* vg = v + ((size_t)hh * TT + (size_t)bl * 64) * DK;
        const int d  = tid & 63;
        const int jh = (tid >> 6) * 16;             // j-pairs [jh, jh+16)
        #pragma unroll 4
        for (int jj = 0; jj < 16; jj++) {
            const int j = jh + jj;
            float a = vg[(size_t)(2 * j)     * DK + d];
            float b = vg[(size_t)(2 * j + 1) * DK + d];
            uint32_t hi, lo;
            split2(a, b, hi, lo);
            *(uint32_t*)(vthi + d * VPITCH + j * 4) = hi;
            *(uint32_t*)(vtlo + d * VPITCH + j * 4) = lo;
        }
    }
    __syncthreads();

    // ---- wait for bucket_kernel's grid (PDL); then read our bucket ----
    cudaGridDependencySynchronize();
    const unsigned short* qbuf = g_qbuf + (size_t)u * BKCAP;
    const int n = g_bcnt[u];

    // ---- 16-query warp tiles; 4 warps stride the tile list ----
    for (int base = warp * 16; base < n; base += 64) {
        // rows this thread touches: gid and gid+8
        const int e0 = base + gid, e1 = base + gid + 8;
        const unsigned short w0 = qbuf[(e0 < n) ? e0 : 0];
        const unsigned short w1 = qbuf[(e1 < n) ? e1 : 0];
        const int qg0 = hh * TQ + (w0 & 0x0FFF);
        const int qg1 = hh * TQ + (w1 & 0x0FFF);
        const int mk0 = (e0 < n) ? (w0 >> 12) : 0;
        const int mk1 = (e1 < n) ? (w1 >> 12) : 0;
        const float* qr0 = q + (size_t)qg0 * DK;
        const float* qr1 = q + (size_t)qg1 * DK;

        // ---- QK: S[16,64] = Q·K^T via 3-term bf16 split ----
        float sc[8][4];
        #pragma unroll
        for (int nt = 0; nt < 8; nt++)
            sc[nt][0] = sc[nt][1] = sc[nt][2] = sc[nt][3] = 0.f;

        #pragma unroll
        for (int kc = 0; kc < 4; kc++) {
            uint32_t ah[4], al[4];
            {
                float2 x0 = *(const float2*)(qr0 + kc * 16 + 2 * tig);
                float2 x1 = *(const float2*)(qr1 + kc * 16 + 2 * tig);
                float2 x2 = *(const float2*)(qr0 + kc * 16 + 2 * tig + 8);
                float2 x3 = *(const float2*)(qr1 + kc * 16 + 2 * tig + 8);
                split2(x0.x, x0.y, ah[0], al[0]);
                split2(x1.x, x1.y, ah[1], al[1]);
                split2(x2.x, x2.y, ah[2], al[2]);
                split2(x3.x, x3.y, ah[3], al[3]);
            }
            #pragma unroll
            for (int nt = 0; nt < 8; nt++) {
                const char* kb = khi + (nt * 8 + gid) * KPITCH + kc * 32 + tig * 4;
                const char* lb = klo + (nt * 8 + gid) * KPITCH + kc * 32 + tig * 4;
                uint32_t bh0 = *(const uint32_t*)(kb);
                uint32_t bh1 = *(const uint32_t*)(kb + 16);
                uint32_t bl0 = *(const uint32_t*)(lb);
                uint32_t bl1 = *(const uint32_t*)(lb + 16);
                MMA(sc[nt][0], sc[nt][1], sc[nt][2], sc[nt][3],
                    ah[0], ah[1], ah[2], ah[3], bh0, bh1);     // Qhi·Khi
                MMA(sc[nt][0], sc[nt][1], sc[nt][2], sc[nt][3],
                    al[0], al[1], al[2], al[3], bh0, bh1);     // Qlo·Khi
                MMA(sc[nt][0], sc[nt][1], sc[nt][2], sc[nt][3],
                    ah[0], ah[1], ah[2], ah[3], bl0, bl1);     // Qhi·Klo
            }
        }

        // ---- softmax partials: p = exp(s/8); l row-sums; P -> bf16 hi/lo ----
        uint32_t phi0[8], phi1[8], plo0[8], plo1[8];
        float sum0 = 0.f, sum1 = 0.f;
        #pragma unroll
        for (int nt = 0; nt < 8; nt++) {
            float p0 = __expf(sc[nt][0] * 0.125f);
            float p1 = __expf(sc[nt][1] * 0.125f);
            float p2 = __expf(sc[nt][2] * 0.125f);
            float p3 = __expf(sc[nt][3] * 0.125f);
            sum0 += p0 + p1;
            sum1 += p2 + p3;
            split2(p0, p1, phi0[nt], plo0[nt]);   // row gid
            split2(p2, p3, phi1[nt], plo1[nt]);   // row gid+8
        }
        sum0 += __shfl_xor_sync(0xFFFFFFFFu, sum0, 1);
        sum0 += __shfl_xor_sync(0xFFFFFFFFu, sum0, 2);
        sum1 += __shfl_xor_sync(0xFFFFFFFFu, sum1, 1);
        sum1 += __shfl_xor_sync(0xFFFFFFFFu, sum1, 2);

        // ---- PV: O[16,64] = P·V via 3-term split ----
        float oc[8][4];
        #pragma unroll
        for (int nt = 0; nt < 8; nt++)
            oc[nt][0] = oc[nt][1] = oc[nt][2] = oc[nt][3] = 0.f;

        #pragma unroll
        for (int kc = 0; kc < 4; kc++) {
            // A fragment (P) chunk kc = S n-tiles 2kc, 2kc+1 (direct mapping)
            const uint32_t pah0 = phi0[2 * kc],     pah1 = phi1[2 * kc];
            const uint32_t pah2 = phi0[2 * kc + 1], pah3 = phi1[2 * kc + 1];
            const uint32_t pal0 = plo0[2 * kc],     pal1 = plo1[2 * kc];
            const uint32_t pal2 = plo0[2 * kc + 1], pal3 = plo1[2 * kc + 1];
            #pragma unroll
            for (int nt = 0; nt < 8; nt++) {
                const char* vb = vthi + (nt * 8 + gid) * VPITCH + kc * 32 + tig * 4;
                const char* wb = vtlo + (nt * 8 + gid) * VPITCH + kc * 32 + tig * 4;
                uint32_t bh0 = *(const uint32_t*)(vb);
                uint32_t bh1 = *(const uint32_t*)(vb + 16);
                uint32_t bl0 = *(const uint32_t*)(wb);
                uint32_t bl1 = *(const uint32_t*)(wb + 16);
                MMA(oc[nt][0], oc[nt][1], oc[nt][2], oc[nt][3],
                    pah0, pah1, pah2, pah3, bh0, bh1);         // Phi·Vhi
                MMA(oc[nt][0], oc[nt][1], oc[nt][2], oc[nt][3],
                    pal0, pal1, pal2, pal3, bh0, bh1);         // Plo·Vhi
                MMA(oc[nt][0], oc[nt][1], oc[nt][2], oc[nt][3],
                    pah0, pah1, pah2, pah3, bl0, bl1);         // Phi·Vlo
            }
        }

        // ---- store flash partials (unnormalized; dup mk==3 fills both) ----
        #pragma unroll
        for (int slot = 0; slot < 2; slot++) {
            const size_t sbase = (size_t)slot * NQG * DK;
            if (mk0 & (1 << slot)) {
                #pragma unroll
                for (int nt = 0; nt < 8; nt++)
                    *(float2*)(g_acc + sbase + (size_t)qg0 * DK + nt * 8 + 2 * tig) =
                        make_float2(oc[nt][0], oc[nt][1]);
                if (tig == 0) {
                    if (slot == 0) g_l2[qg0].x = sum0; else g_l2[qg0].y = sum0;
                }
            }
            if (mk1 & (1 << slot)) {
                #pragma unroll
                for (int nt = 0; nt < 8; nt++)
                    *(float2*)(g_acc + sbase + (size_t)qg1 * DK + nt * 8 + 2 * tig) =
                        make_float2(oc[nt][2], oc[nt][3]);
                if (tig == 0) {
                    if (slot == 0) g_l2[qg1].x = sum1; else g_l2[qg1].y = sum1;
                }
            }
        }
    }
}

// ---------------------------------------------------------------------------
// Combine: out = (acc0 + acc1) / (l0 + l1). PDL: sync on partial's grid,
// then reset bucket counters (now provably after all partial reads).
// ---------------------------------------------------------------------------
__global__ __launch_bounds__(256)
void combine_kernel(float* __restrict__ out)
{
    cudaGridDependencySynchronize();
    if (blockIdx.x == 0 && threadIdx.x < NUNITS / 2) {
        g_bcnt[threadIdx.x] = 0;
        g_bcnt[threadIdx.x + NUNITS / 2] = 0;
    }
    const int t  = blockIdx.x * 256 + threadIdx.x;
    const int qg = t >> 4;
    const float2 ll = g_l2[qg];
    const float4 a  = ((const float4*)g_acc)[t];
    const float4 b  = ((const float4*)g_acc)[NQG * 16 + t];
    const float inv = 1.0f / (ll.x + ll.y);
    float4 o;
    o.x = (a.x + b.x) * inv;
    o.y = (a.y + b.y) * inv;
    o.z = (a.z + b.z) * inv;
    o.w = (a.w + b.w) * inv;
    ((float4*)out)[t] = o;
}

// ---------------------------------------------------------------------------
static void launch_pdl(const void* fn, dim3 grid, dim3 block,
                       void** args)
{
    cudaLaunchConfig_t cfg = {};
    cfg.gridDim  = grid;
    cfg.blockDim = block;
    cfg.stream   = 0;
    cudaLaunchAttribute attr[1];
    attr[0].id = cudaLaunchAttributeProgrammaticStreamSerialization;
    attr[0].val.programmaticStreamSerializationAllowed = 1;
    cfg.attrs    = attr;
    cfg.numAttrs = 1;
    cudaLaunchKernelExC(&cfg, fn, args);
}

extern "C" void kernel_launch(void* const* d_in, const int* in_sizes, int n_in,
                              void* d_out, int out_size)
{
    const float* q = nullptr; const float* k = nullptr; const float* v = nullptr;
    const int* idx = nullptr;
    for (int i = 0; i < n_in; i++) {
        const int s = in_sizes[i];
        if (s == HH * TQ * DK && !q)  q = (const float*)d_in[i];       // 1,048,576
        else if (s == HH * TT * DK) {                                   // 2,097,152
            if (!k) k = (const float*)d_in[i];
            else if (!v) v = (const float*)d_in[i];
        }
        else if (s == HH * TQ * 2)    idx = (const int*)d_in[i];        // 32,768
    }

    bucket_kernel<<<NQG / 256, 256>>>(idx);

    {   // partial: PDL-overlapped with bucket (stages K/V before the sync)
        void* args[3] = { (void*)&q, (void*)&k, (void*)&v };
        launch_pdl((const void*)partial_kernel,
                   dim3(NUNITS), dim3(128), args);
    }
    {   // combine: PDL to hide launch latency behind partial's tail
        float* outp = (float*)d_out;
        void* args[1] = { (void*)&outp };
        launch_pdl((const void*)combine_kernel,
                   dim3((NQG * 16) / 256), dim3(256), args);
    }
}